// round 4
// baseline (speedup 1.0000x reference)
#include <cuda_runtime.h>
#include <math.h>

#define BB 256
#define HH 256
#define NLY 6
#define SS 128
#define G3 768

struct Ptrs {
  const float *x, *Wih0, *Wih, *Whh, *bih, *bhh, *h0;
  const float *aW1, *aW2, *aW3, *aW4;
  const float *sdW1,*sdb1,*sdW2,*sdb2,*sdW3,*sdb3,*sdW4,*sdb4;
  const float *odW1,*odb1,*odW2,*odb2,*odW3,*odb3,*odW4,*odb4;
  float* out;
};

// scratch (device globals -- no allocation allowed)
__device__ __align__(16) float g_h[2][NLY][BB][HH];
__device__ __align__(16) float g_hpre[NLY][BB][HH];
__device__ __align__(16) float g_sh[NLY][BB][HH];
__device__ __align__(16) float g_Gi[NLY][BB][G3];
__device__ __align__(16) float g_Gh[NLY][BB][G3];
__device__ __align__(16) float g_A3[NLY][BB][512];
// precomputed fused-attn weights
__device__ __align__(16) float g_W2dT[NLY][512][512];
__device__ __align__(16) float g_W3d[NLY][512][512];
__device__ __align__(16) float g_W1T[NLY][256][256];
__device__ __align__(16) float g_Md[NLY][512][512];
__device__ __align__(16) float g_P[NLY][512][512];

#define YSEQ_OFF 8388608ul
#define YONE_OFF 9437184ul

typedef unsigned long long u64;

__device__ __forceinline__ u64 dup2(float a) {
  u64 d; unsigned ai = __float_as_uint(a);
  asm("mov.b64 %0, {%1, %1};" : "=l"(d) : "r"(ai));
  return d;
}
__device__ __forceinline__ void fma2(u64& acc, u64 a, u64 b) {
  asm("fma.rn.f32x2 %0, %1, %2, %0;" : "+l"(acc) : "l"(a), "l"(b));
}
__device__ __forceinline__ void unpack2(u64 v, float& lo, float& hi) {
  unsigned l_, h_;
  asm("mov.b64 {%0, %1}, %2;" : "=r"(l_), "=r"(h_) : "l"(v));
  lo = __uint_as_float(l_); hi = __uint_as_float(h_);
}

// ---------------------------------------------------------------------------
// GEMM core: TM x 128 output tile, 256 threads, TK=8, double-buffered smem.
// N-paired f32x2 accumulators: acc[i][j] = cols (n0+tx*8+2j, +1), row ty*IM+i.
// A is a concat source: col c<256 from A0, c>=256 from A1 (both stride lda;
// for plain GEMMs pass A1 = A0 + 256 or anything if K<=256).
// W row-major [128 rows of this n-tile, K], stride ldb.
// ---------------------------------------------------------------------------
template<int TM>
__device__ __forceinline__ void gemm_core(
    const float* __restrict__ A0, const float* __restrict__ A1, int lda,
    const float* __restrict__ W, int ldb, int K,
    u64 acc[TM/16][4], float* As, float* Bs)
{
  constexpr int IM = TM / 16;
  const int t  = threadIdx.x;
  const int tx = t & 15, ty = t >> 4;
  int ar, ak;
  if (TM == 64) { ar = t >> 2; ak = (t & 3) * 2; }
  else          { ar = t >> 3; ak = (t & 7); }
  const int br = t >> 1, bo = (t & 1) * 4;

  float a0v, a1v; float4 rb;
  auto loadT = [&](int k0) {
    int c = k0 + ak;
    const float* base = (c < 256) ? (A0 + c) : (A1 + (c - 256));
    const float* pa = base + (size_t)ar * lda;
    if (TM == 64) { float2 v = *(const float2*)pa; a0v = v.x; a1v = v.y; }
    else          { a0v = *pa; }
    rb = *(const float4*)(W + (size_t)br * ldb + k0 + bo);
  };
  auto storeT = [&](int buf) {
    float* as = As + buf * (8 * TM);
    float* bs = Bs + buf * 1024;
    if (TM == 64) { as[ak*TM + ar] = a0v; as[(ak+1)*TM + ar] = a1v; }
    else          { as[ak*TM + ar] = a0v; }
    bs[(bo+0)*128 + br] = rb.x; bs[(bo+1)*128 + br] = rb.y;
    bs[(bo+2)*128 + br] = rb.z; bs[(bo+3)*128 + br] = rb.w;
  };
  auto compute = [&](int buf) {
    const float* as = As + buf * (8 * TM) + ty * IM;
    const float* bs = Bs + buf * 1024 + tx * 8;
#pragma unroll
    for (int kk = 0; kk < 8; kk++) {
      float av[IM];
      if (TM == 64) {
        float4 a4v = *(const float4*)(as + kk * TM);
        av[0]=a4v.x; av[1]=a4v.y; av[2]=a4v.z; av[3]=a4v.w;
      } else {
        float2 a2v = *(const float2*)(as + kk * TM);
        av[0]=a2v.x; av[1]=a2v.y;
      }
      ulonglong2 b0 = *(const ulonglong2*)(bs + kk * 128);
      ulonglong2 b1 = *(const ulonglong2*)(bs + kk * 128 + 4);
      u64 bp[4] = {b0.x, b0.y, b1.x, b1.y};
      u64 ad[IM];
#pragma unroll
      for (int i = 0; i < IM; i++) ad[i] = dup2(av[i]);
#pragma unroll
      for (int i = 0; i < IM; i++)
#pragma unroll
        for (int j = 0; j < 4; j++) fma2(acc[i][j], ad[i], bp[j]);
    }
  };

  const int nb = K >> 3;
  loadT(0); storeT(0); __syncthreads();
  for (int kb = 1; kb < nb; kb++) {
    loadT(kb << 3);
    compute((kb - 1) & 1);
    storeT(kb & 1);
    __syncthreads();
  }
  compute((nb - 1) & 1);
}

template<int IM>
__device__ __forceinline__ void unp(u64 acc[IM][4], float v[IM][8]) {
#pragma unroll
  for (int i = 0; i < IM; i++)
#pragma unroll
    for (int j = 0; j < 4; j++)
      unpack2(acc[i][j], v[i][2*j], v[i][2*j+1]);
}

// ---------------------------------------------------------------------------
// Prep: build dense shuffled W2/W3 (transposed as needed), W1^T, then
// Md = W3d @ W2d and P = [Md[:,:256]@W1 | Md[:,256:]@W1].
// ---------------------------------------------------------------------------
__global__ void prep_zero() {
  int i = blockIdx.x * 256 + threadIdx.x;
  if (i < NLY * 512 * 512) {
    ((float*)g_W2dT)[i] = 0.f;
    ((float*)g_W3d)[i] = 0.f;
  }
}

__global__ void prep_scatter(Ptrs P) {
  int i = blockIdx.x * 256 + threadIdx.x;
  if (i >= NLY * 4 * 128 * 128) return;
  int l = i >> 16; int r = i & 65535;
  int g = r >> 14; int j = (r >> 7) & 127; int m = r & 127;
  int v = g * 128 + m;
  int c = ((v & 3) << 7) + (v >> 2);
  g_W2dT[l][c][g*128 + j] = P.aW2[((size_t)l*128 + j)*128 + m];
  g_W3d[l][g*128 + j][c]  = P.aW3[((size_t)l*128 + j)*128 + m];
}

__global__ void prep_w1t(Ptrs P) {
  int i = blockIdx.x * 256 + threadIdx.x;
  if (i >= NLY * 256 * 256) return;
  int l = i >> 16; int r = i & 65535; int c1 = r >> 8; int k = r & 255;
  g_W1T[l][k][c1] = P.aW1[(size_t)l*65536 + (size_t)c1*256 + k];
}

__global__ void __launch_bounds__(256) prep_md() {
  __shared__ __align__(16) float As[2*8*64], Bs[2*8*128];
  int l = blockIdx.y;
  int m0 = (blockIdx.x & 7) << 6, n0 = (blockIdx.x >> 3) << 7;
  const float* A0 = &g_W3d[l][m0][0];
  const float* W  = &g_W2dT[l][n0][0];
  u64 acc[4][4] = {};
  gemm_core<64>(A0, A0 + 256, 512, W, 512, 512, acc, As, Bs);
  float v[4][8]; unp<4>(acc, v);
  int tx = threadIdx.x & 15, ty = threadIdx.x >> 4;
#pragma unroll
  for (int r = 0; r < 4; r++) {
    int m = m0 + ty*4 + r;
    float* po = &g_Md[l][m][n0 + tx*8];
    *(float4*)(po)     = make_float4(v[r][0], v[r][1], v[r][2], v[r][3]);
    *(float4*)(po + 4) = make_float4(v[r][4], v[r][5], v[r][6], v[r][7]);
  }
}

__global__ void __launch_bounds__(256) prep_p() {
  __shared__ __align__(16) float As[2*8*64], Bs[2*8*128];
  int l = blockIdx.y;
  int m0 = (blockIdx.x & 7) << 6;
  int nt = blockIdx.x >> 3;              // 0..3
  int half = nt >> 1;
  const float* A0 = &g_Md[l][m0][half * 256];
  const float* W  = &g_W1T[l][(nt & 1) * 128][0];
  u64 acc[4][4] = {};
  gemm_core<64>(A0, A0, 512, W, 256, 256, acc, As, Bs);
  float v[4][8]; unp<4>(acc, v);
  int tx = threadIdx.x & 15, ty = threadIdx.x >> 4;
#pragma unroll
  for (int r = 0; r < 4; r++) {
    int m = m0 + ty*4 + r;
    float* po = &g_P[l][m][nt*128 + tx*8];
    *(float4*)(po)     = make_float4(v[r][0], v[r][1], v[r][2], v[r][3]);
    *(float4*)(po + 4) = make_float4(v[r][4], v[r][5], v[r][6], v[r][7]);
  }
}

// ---------------------------------------------------------------------------
// Stage 1: Gi = inp @ Wih^T (z=0) ; Gh = h_prev @ Whh^T (z=1). grid(24,nA,2)
// ---------------------------------------------------------------------------
__global__ void __launch_bounds__(256) stage1_k(Ptrs P, int w, int lmin, int pp) {
  __shared__ __align__(16) float As[2*8*64], Bs[2*8*128];
  int l = lmin + blockIdx.y, t = w - l;
  int i = blockIdx.x;
  int m0 = (i & 3) << 6, n0 = (i >> 2) << 7;
  const float *A0, *W; int lda, K; float* out;
  if (blockIdx.z == 0) {
    if (l == 0) { A0 = P.x + (size_t)t*128 + (size_t)m0*16384; lda = 16384; K = 128;
                  W = P.Wih0 + (size_t)n0 * 128; }
    else        { A0 = &g_h[pp][l-1][m0][0]; lda = HH; K = HH;
                  W = P.Wih + ((size_t)(l-1)*G3 + n0) * HH; }
    out = &g_Gi[l][0][0];
  } else {
    if (t == 0) { A0 = P.h0 + l*HH; lda = 0; }
    else        { A0 = &g_h[pp][l][m0][0]; lda = HH; }
    K = HH; W = P.Whh + ((size_t)l*G3 + n0) * HH;
    out = &g_Gh[l][0][0];
  }
  u64 acc[4][4] = {};
  gemm_core<64>(A0, A0, lda, W, K, K, acc, As, Bs);
  float v[4][8]; unp<4>(acc, v);
  int tx = threadIdx.x & 15, ty = threadIdx.x >> 4;
#pragma unroll
  for (int r = 0; r < 4; r++) {
    int m = m0 + ty*4 + r;
    float* po = out + (size_t)m * G3 + n0 + tx*8;
    *(float4*)(po)     = make_float4(v[r][0], v[r][1], v[r][2], v[r][3]);
    *(float4*)(po + 4) = make_float4(v[r][4], v[r][5], v[r][6], v[r][7]);
  }
}

// ---------------------------------------------------------------------------
// Stage 2: gates -> hpre, warp-synchronous bitonic sort -> sh. grid(32,nA)
// ---------------------------------------------------------------------------
__global__ void __launch_bounds__(256) gatesort_k(Ptrs P, int w, int lmin, int pp) {
  int l = lmin + blockIdx.y, t = w - l;
  int warp = threadIdx.x >> 5, lane = threadIdx.x & 31;
  int b = blockIdx.x * 8 + warp;
  __shared__ float v[8][256];
  const float* bi = P.bih + l * G3;
  const float* bh = P.bhh + l * G3;
#pragma unroll
  for (int q = 0; q < 8; q++) {
    int j = lane + (q << 5);
    float gi0 = g_Gi[l][b][j]      + bi[j];
    float gi1 = g_Gi[l][b][j+256]  + bi[j+256];
    float gi2 = g_Gi[l][b][j+512]  + bi[j+512];
    float gh0 = g_Gh[l][b][j]      + bh[j];
    float gh1 = g_Gh[l][b][j+256]  + bh[j+256];
    float gh2 = g_Gh[l][b][j+512]  + bh[j+512];
    float r = 1.f / (1.f + expf(-(gi0 + gh0)));
    float z = 1.f / (1.f + expf(-(gi1 + gh1)));
    float n = tanhf(gi2 + r * gh2);
    float hp = (t == 0) ? P.h0[l * HH + j] : g_h[pp][l][b][j];
    float hv = (1.f - z) * n + z * hp;
    g_hpre[l][b][j] = hv;
    v[warp][j] = hv;
  }
  __syncwarp();
  for (int k = 2; k <= 256; k <<= 1) {
    for (int jj = k >> 1; jj > 0; jj >>= 1) {
#pragma unroll
      for (int q = 0; q < 8; q++) {
        int idx = lane + (q << 5);
        int ixj = idx ^ jj;
        if (ixj > idx) {
          float a = v[warp][idx], c = v[warp][ixj];
          bool up = ((idx & k) == 0);
          if ((a > c) == up) { v[warp][idx] = c; v[warp][ixj] = a; }
        }
      }
      __syncwarp();
    }
  }
#pragma unroll
  for (int q = 0; q < 8; q++) {
    int j = lane + (q << 5);
    g_sh[l][b][j] = v[warp][j];
  }
}

// ---------------------------------------------------------------------------
// Stage 3 (fused a1+a2+a3): A3 = relu([hpre | sh] @ P^T). grid(16,nA)
// ---------------------------------------------------------------------------
__global__ void __launch_bounds__(256) attn_k(int lmin) {
  __shared__ __align__(16) float As[2*8*64], Bs[2*8*128];
  int l = lmin + blockIdx.y;
  int i = blockIdx.x;
  int m0 = (i & 3) << 6, n0 = (i >> 2) << 7;
  const float* A0 = &g_hpre[l][m0][0];
  const float* A1 = &g_sh[l][m0][0];
  const float* W  = &g_P[l][n0][0];
  u64 acc[4][4] = {};
  gemm_core<64>(A0, A1, 256, W, 512, 512, acc, As, Bs);
  float v[4][8]; unp<4>(acc, v);
  int tx = threadIdx.x & 15, ty = threadIdx.x >> 4;
#pragma unroll
  for (int r = 0; r < 4; r++) {
    int m = m0 + ty*4 + r;
#pragma unroll
    for (int q = 0; q < 8; q++) v[r][q] = fmaxf(v[r][q], 0.f);
    float* po = &g_A3[l][m][n0 + tx*8];
    *(float4*)(po)     = make_float4(v[r][0], v[r][1], v[r][2], v[r][3]);
    *(float4*)(po + 4) = make_float4(v[r][4], v[r][5], v[r][6], v[r][7]);
  }
}

// ---------------------------------------------------------------------------
// Stage 4: a4 = A3 @ W4^T ; h = hpre * sigmoid(a4). grid(16,nA), TM=32.
// ---------------------------------------------------------------------------
__global__ void __launch_bounds__(256) a4_k(Ptrs P, int w, int lmin, int p) {
  __shared__ __align__(16) float As[2*8*64], Bs[2*8*128];
  int l = lmin + blockIdx.y, t = w - l;
  int i = blockIdx.x;
  int m0 = (i & 7) << 5, n0 = (i >> 3) << 7;
  const float* A0 = &g_A3[l][m0][0];
  const float* W  = P.aW4 + ((size_t)l*256 + n0) * 512;
  u64 acc[2][4] = {};
  gemm_core<32>(A0, A0 + 256, 512, W, 512, 512, acc, As, Bs);
  float v[2][8]; unp<2>(acc, v);
  int tx = threadIdx.x & 15, ty = threadIdx.x >> 4;
#pragma unroll
  for (int r = 0; r < 2; r++) {
    int m = m0 + ty*2 + r;
    int n = n0 + tx*8;
#pragma unroll
    for (int q = 0; q < 8; q++) {
      float hv = g_hpre[l][m][n+q] * (1.f / (1.f + expf(-v[r][q])));
      g_h[p][l][m][n+q] = hv;
      if (l == NLY - 1)
        P.out[(size_t)m * 32768 + (size_t)t * 256 + n + q] = hv;
    }
  }
}

// ---------------------------------------------------------------------------
__global__ void seqdec_kernel(Ptrs P) {
  int idx = blockIdx.x * blockDim.x + threadIdx.x;
  int b = idx >> 7, s = idx & 127;
  const float* e = P.out + (size_t)b * 32768 + (size_t)s * 256;
  float a1[8][4], a2[8][4], a3[8][4];
#pragma unroll
  for (int g = 0; g < 8; g++)
#pragma unroll
    for (int o = 0; o < 4; o++) {
      float sum = P.sdb1[o];
#pragma unroll
      for (int m = 0; m < 32; m++) sum += e[g*32+m] * P.sdW1[o*32+m];
      a1[g][o] = sum;
    }
#pragma unroll
  for (int i = 0; i < 8; i++)
#pragma unroll
    for (int o = 0; o < 4; o++) {
      float sum = P.sdb2[o];
#pragma unroll
      for (int j = 0; j < 4; j++) {
        int f = i*4 + j;
        sum += a1[f & 7][f >> 3] * P.sdW2[o*4+j];
      }
      a2[i][o] = sum;
    }
#pragma unroll
  for (int i = 0; i < 8; i++)
#pragma unroll
    for (int o = 0; o < 4; o++) {
      float sum = P.sdb3[o];
#pragma unroll
      for (int j = 0; j < 4; j++) {
        int f = i*4 + j;
        sum += a2[f & 7][f >> 3] * P.sdW3[o*4+j];
      }
      a3[i][o] = sum;
    }
#pragma unroll
  for (int o = 0; o < 4; o++)
#pragma unroll
    for (int wv = 0; wv < 8; wv++) {
      float sum = P.sdb4[wv];
#pragma unroll
      for (int g = 0; g < 8; g++) {
        int f = o*8 + g;
        sum += a3[f >> 2][f & 3] * P.sdW4[wv*8+g];
      }
      P.out[YSEQ_OFF + (size_t)b * 4096 + (size_t)(s*8 + wv) * 4 + o] = sum;
    }
}

// ---------------------------------------------------------------------------
__global__ void onedec_kernel(Ptrs P) {
  int b = blockIdx.x;
  __shared__ float acc[10][4];
  int tid = threadIdx.x;
  if (tid < 10) {
    int s = 118 + tid;
    const float* e = P.out + (size_t)b * 32768 + (size_t)s * 256;
    float o1[8][4], o2[8][4], o3[8][4];
#pragma unroll
    for (int g = 0; g < 8; g++)
#pragma unroll
      for (int o = 0; o < 4; o++) {
        float sum = P.odb1[o];
#pragma unroll
        for (int m = 0; m < 32; m++) sum += e[g*32+m] * P.odW1[o*32+m];
        o1[g][o] = sum;
      }
#pragma unroll
    for (int i = 0; i < 8; i++)
#pragma unroll
      for (int o = 0; o < 4; o++) {
        float sum = P.odb2[o];
#pragma unroll
        for (int j = 0; j < 4; j++) {
          int f = i*4 + j;
          sum += o1[f & 7][f >> 3] * P.odW2[o*4+j];
        }
        o2[i][o] = sum;
      }
#pragma unroll
    for (int i = 0; i < 8; i++)
#pragma unroll
      for (int o = 0; o < 4; o++) {
        float sum = P.odb3[o];
#pragma unroll
        for (int j = 0; j < 4; j++) {
          int f = i*4 + j;
          sum += o2[f & 7][f >> 3] * P.odW3[o*4+j];
        }
        o3[i][o] = fmaxf(sum, 0.f);
      }
#pragma unroll
    for (int c = 0; c < 4; c++) {
      float sum = P.odb4[c];
#pragma unroll
      for (int f = 0; f < 32; f++) sum += o3[f >> 2][f & 3] * P.odW4[c*32+f];
      acc[tid][c] = 1.f / (1.f + expf(-sum));
    }
  }
  __syncthreads();
  if (tid < 4) {
    float s = 0.f;
#pragma unroll
    for (int i = 0; i < 10; i++) s += acc[i][tid];
    P.out[YONE_OFF + (size_t)b * 4 + tid] = s * 0.1f;
  }
}

// ---------------------------------------------------------------------------
extern "C" void kernel_launch(void* const* d_in, const int* in_sizes, int n_in,
                              void* d_out, int out_size) {
  (void)in_sizes; (void)n_in; (void)out_size;
  Ptrs P;
  P.x    = (const float*)d_in[0];
  P.Wih0 = (const float*)d_in[1];
  P.Wih  = (const float*)d_in[2];
  P.Whh  = (const float*)d_in[3];
  P.bih  = (const float*)d_in[4];
  P.bhh  = (const float*)d_in[5];
  P.h0   = (const float*)d_in[6];
  P.aW1  = (const float*)d_in[7];
  P.aW2  = (const float*)d_in[8];
  P.aW3  = (const float*)d_in[9];
  P.aW4  = (const float*)d_in[10];
  P.sdW1 = (const float*)d_in[11];
  P.sdb1 = (const float*)d_in[12];
  P.sdW2 = (const float*)d_in[13];
  P.sdb2 = (const float*)d_in[14];
  P.sdW3 = (const float*)d_in[15];
  P.sdb3 = (const float*)d_in[16];
  P.sdW4 = (const float*)d_in[17];
  P.sdb4 = (const float*)d_in[18];
  P.odW1 = (const float*)d_in[19];
  P.odb1 = (const float*)d_in[20];
  P.odW2 = (const float*)d_in[21];
  P.odb2 = (const float*)d_in[22];
  P.odW3 = (const float*)d_in[23];
  P.odb3 = (const float*)d_in[24];
  P.odW4 = (const float*)d_in[25];
  P.odb4 = (const float*)d_in[26];
  P.out  = (float*)d_out;

  // prep: fold SortAttn shuffles + W1/W2/W3 into one dense P per layer
  prep_zero<<<6144, 256>>>();
  prep_scatter<<<1536, 256>>>(P);
  prep_w1t<<<1536, 256>>>(P);
  prep_md<<<dim3(32, NLY), 256>>>();
  prep_p<<<dim3(32, NLY), 256>>>();

  for (int w = 0; w < SS + NLY - 1; w++) {
    int lmin = w - (SS - 1); if (lmin < 0) lmin = 0;
    int lmax = (w < NLY - 1) ? w : NLY - 1;
    int nA = lmax - lmin + 1;
    int pp = (w + 1) & 1;
    int p  = w & 1;
    stage1_k<<<dim3(24, nA, 2), 256>>>(P, w, lmin, pp);
    gatesort_k<<<dim3(32, nA), 256>>>(P, w, lmin, pp);
    attn_k<<<dim3(16, nA), 256>>>(lmin);
    a4_k<<<dim3(16, nA), 256>>>(P, w, lmin, p);
  }

  seqdec_kernel<<<128, 256>>>(P);
  onedec_kernel<<<256, 32>>>(P);
}